// round 17
// baseline (speedup 1.0000x reference)
#include <cuda_runtime.h>
#include <math.h>

// Problem dims
#define TT   8192
#define DIN  2048
#define DD   512
#define HH   512
#define AA   18
#define H3   (3*HH)       // 1536

// GRU scan: 64 persistent CTAs x 256 threads. Warp j of CTA blk owns h-index
// blk*8+j. Lane = gate*8+seg (24 compute lanes), lanes 24-26 X-prefetch,
// 252 pollers overlay all warps.
#define GC   64
#define HPC  8
#define GTHREADS 256

// Output layout (flattened concat of (policy, value, hT))
#define P_OFF  0
#define V_OFF  (TT*AA)            // 147456
#define HT_OFF (TT*AA + TT)       // 155648

// ---------------- device scratch (no allocations allowed) ----------------
__device__ float g_z1[TT*DD];
__device__ float g_z2[TT*DD];
__device__ float g_X [TT*H3];
__device__ float g_seq[TT*HH];
// Per-h-element publish slot: {f32 h, u32 flag} in ONE 8B atom, written with a
// single st.release.gpu.b64 — matching flag implies valid payload in-atom.
// Slot in buf b is read at steps t≡b (mod 2) and rewritten at t+1's publish;
// the all-to-all read-before-publish chain makes the 1-step reuse safe.
__device__ __align__(16) unsigned long long g_hs[2][HH];

__device__ __forceinline__ float sigmoidf_(float x) {
    return 1.0f / (1.0f + __expf(-x));
}

__device__ __forceinline__ unsigned long long pack_hf(float h, unsigned f) {
    unsigned long long r;
    asm("mov.b64 %0, {%1, %2};" : "=l"(r) : "f"(h), "r"(f));
    return r;
}
__device__ __forceinline__ void unpack_hf(unsigned long long v, float& h, unsigned& f) {
    asm("mov.b64 {%0, %1}, %2;" : "=f"(h), "=r"(f) : "l"(v));
}
__device__ __forceinline__ unsigned long long ld_rlx64(const unsigned long long* p) {
    unsigned long long v;
    asm volatile("ld.global.relaxed.gpu.b64 %0, [%1];" : "=l"(v) : "l"(p));
    return v;
}
__device__ __forceinline__ void st_rel64(unsigned long long* p, unsigned long long v) {
    asm volatile("st.release.gpu.b64 [%0], %1;" :: "l"(p), "l"(v) : "memory");
}

// Packed fp32x2 FMA (Blackwell FFMA2; PTX-only form). acc = w2*h2 + acc lanewise.
__device__ __forceinline__ void ffma2(unsigned long long& acc,
                                      unsigned long long w2,
                                      unsigned long long h2) {
    asm("fma.rn.f32x2 %0, %1, %2, %0;" : "+l"(acc) : "l"(w2), "l"(h2));
}
__device__ __forceinline__ unsigned long long pack2(float lo, float hi) {
    unsigned long long r;
    asm("mov.b64 %0, {%1, %2};" : "=l"(r) : "f"(lo), "f"(hi));
    return r;
}
__device__ __forceinline__ void unpack2(unsigned long long v, float& lo, float& hi) {
    asm("mov.b64 {%0, %1}, %2;" : "=f"(lo), "=f"(hi) : "l"(v));
}

// ---------------- fp32 SGEMM: C = act(A[MxK] @ B[KxN] + bias[N]) ----------------
// 128x128 tile, BK=8, 256 threads, 8x8 micro-tile, packed FFMA2 inner product.
template<bool RELU>
__global__ __launch_bounds__(256)
void sgemm_bias(const float* __restrict__ A, const float* __restrict__ B,
                const float* __restrict__ bias, float* __restrict__ C,
                int M, int N, int K)
{
    __shared__ float As[8][128];
    __shared__ float Bs[8][128];

    const int tid = threadIdx.x;
    const int bm = blockIdx.y * 128;
    const int bn = blockIdx.x * 128;

    const int arow = tid >> 1;
    const int acol = (tid & 1) << 2;
    const int brow = tid >> 5;
    const int bcol = (tid & 31) << 2;

    const int ty = tid >> 4, tx = tid & 15;
    const int row0 = ty << 3;
    const int col0 = tx << 3;

    unsigned long long c2[8][4];
    #pragma unroll
    for (int i = 0; i < 8; i++)
        #pragma unroll
        for (int j = 0; j < 4; j++) c2[i][j] = 0ULL;

    for (int k0 = 0; k0 < K; k0 += 8) {
        float4 a4 = *(const float4*)&A[(size_t)(bm + arow) * K + k0 + acol];
        As[acol + 0][arow] = a4.x;
        As[acol + 1][arow] = a4.y;
        As[acol + 2][arow] = a4.z;
        As[acol + 3][arow] = a4.w;
        *(float4*)&Bs[brow][bcol] =
            *(const float4*)&B[(size_t)(k0 + brow) * N + bn + bcol];
        __syncthreads();

        #pragma unroll
        for (int kk = 0; kk < 8; kk++) {
            float4 a0 = *(const float4*)&As[kk][row0];
            float4 a1 = *(const float4*)&As[kk][row0 + 4];
            const ulonglong2* bp = (const ulonglong2*)&Bs[kk][col0];
            ulonglong2 b01 = bp[0];
            ulonglong2 b23 = bp[1];
            float ar[8] = {a0.x,a0.y,a0.z,a0.w,a1.x,a1.y,a1.z,a1.w};
            #pragma unroll
            for (int i = 0; i < 8; i++) {
                unsigned long long ad = pack2(ar[i], ar[i]);
                ffma2(c2[i][0], ad, b01.x);
                ffma2(c2[i][1], ad, b01.y);
                ffma2(c2[i][2], ad, b23.x);
                ffma2(c2[i][3], ad, b23.y);
            }
        }
        __syncthreads();
    }

    #pragma unroll
    for (int i = 0; i < 8; i++) {
        #pragma unroll
        for (int j = 0; j < 4; j++) {
            float lo, hi;
            unpack2(c2[i][j], lo, hi);
            float v0 = lo + bias[bn + col0 + 2 * j];
            float v1 = hi + bias[bn + col0 + 2 * j + 1];
            if (RELU) { v0 = fmaxf(v0, 0.0f); v1 = fmaxf(v1, 0.0f); }
            float2 o = make_float2(v0, v1);
            *(float2*)&C[(size_t)(bm + row0 + i) * N + bn + col0 + 2 * j] = o;
        }
    }
}

// ---------------- init: buf0 <- {h0, flag 0}; buf1 cleared ----------------
__global__ void init_kernel(const float* __restrict__ prev_hidden)
{
    int l = threadIdx.x;                       // 512 threads
    g_hs[0][l] = pack_hf(prev_hidden[l], 0u);  // step-0 publish
    g_hs[1][l] = pack_hf(0.0f, 0u);            // clear stale (replay safety:
                                               // buf1 carries odd flags only)
}

// ---------------- persistent GRU scan ----------------
// Warp j of CTA blk computes h[blk*8+j]. Lane = gate*8+seg: each compute lane
// dots Ug[seg*64 .. +64)[gate*512+blk*8+j] against h[seg*64..). The 3 gate
// groups read IDENTICAL sh_h addresses -> 3-way LDS broadcast (1 wavefront per
// LDS.128). seg-reduce via 3 shfl_xor; gates gathered warp-locally from lanes
// 0/8/16 (+X from lanes 24-26) -> lane 0 computes hn and publishes one 8B atom.
// ONE __syncthreads per step; sh_h double-buffered by parity for race freedom.
__global__ __launch_bounds__(GTHREADS, 1)
void gru_kernel(const float* __restrict__ Ug, const float* __restrict__ bg,
                const float* __restrict__ prev_hidden, float* __restrict__ out)
{
    __shared__ float sh_h[2][8 * 68];  // phys(l) = (l>>6)*68 + (l&63)

    const int tid  = threadIdx.x;
    const int blk  = blockIdx.x;
    const int wj   = tid >> 5;         // warp index = local h index j (0..7)
    const int lane = tid & 31;
    const int g    = lane >> 3;        // 0..2 compute, 3 = aux lanes
    const int s    = lane & 7;
    const bool isC = (lane < 24);
    const int gcol = (isC ? g : 0) * HH + blk * HPC + wj;

    // Weight slice packed as fp32 pairs: wp[i] = {Ug[s*64+2i][gcol], Ug[s*64+2i+1][gcol]}
    unsigned long long wp[32];
    if (isC) {
        #pragma unroll
        for (int i = 0; i < 32; i++) {
            float w0 = Ug[(size_t)(s * 64 + 2 * i)     * H3 + gcol];
            float w1 = Ug[(size_t)(s * 64 + 2 * i + 1) * H3 + gcol];
            wp[i] = pack2(w0, w1);
        }
    }
    const float brec = isC ? bg[H3 + gcol] : 0.0f;
    // lane 0 gathers the three recurrent biases once (lanes 0/8/16 hold them)
    const float brz = __shfl_sync(0xffffffffu, brec, 0);
    const float brr = __shfl_sync(0xffffffffu, brec, 8);
    const float brh = __shfl_sync(0xffffffffu, brec, 16);

    // X prefetch lanes 24..26: lane 24+gx holds X[t][gx*512+blk*8+wj]
    const bool isXl = (lane >= 24 && lane < 27);
    const int xgc = (lane - 24) * HH + blk * HPC + wj;
    float xv = isXl ? g_X[xgc] : 0.0f;         // X[0]

    // Poller mapping: threads 0..251 each own one foreign PAIR of 8B slots
    // (2 adjacent h-indices, same 16B). Own pairs blk*4..blk*4+3 excluded.
    const bool isPoll = (tid < (HH / 2) - 4);  // 252
    int pl0 = 0, pl1 = 0;
    if (isPoll) {
        int pr = tid + (tid >= blk * 4 ? 4 : 0);
        pl0 = 2 * pr; pl1 = 2 * pr + 1;
    }

    // lane 0 of warp j keeps its own h in a register; stage into buf 0
    float hprev = 0.0f;
    if (lane == 0) {
        hprev = prev_hidden[blk * HPC + wj];
        int l = blk * HPC + wj;
        sh_h[0][(l >> 6) * 68 + (l & 63)] = hprev;
    }

    for (int t = 0; t < TT; t++) {
        const int b = t & 1;

        if (isPoll) {
            const unsigned long long* p0 = &g_hs[b][pl0];
            const unsigned long long* p1 = &g_hs[b][pl1];
            float ha, hb; unsigned fa, fb;
            do {
                unsigned long long va = ld_rlx64(p0);
                unsigned long long vb = ld_rlx64(p1);
                unpack_hf(va, ha, fa);
                unpack_hf(vb, hb, fb);
            } while (fa != (unsigned)t || fb != (unsigned)t);
            sh_h[b][(pl0 >> 6) * 68 + (pl0 & 63)] = ha;
            sh_h[b][(pl1 >> 6) * 68 + (pl1 & 63)] = hb;
        }
        __syncthreads();                       // bar1: all h_t staged in buf b

        // 64-elem dot per compute lane: 32 packed FFMA2, broadcast LDS.
        float r = 0.0f;
        if (isC) {
            const ulonglong2* hp = (const ulonglong2*)&sh_h[b][s * 68];
            unsigned long long acc01 = 0ULL, acc23 = 0ULL;
            #pragma unroll
            for (int i = 0; i < 16; i++) {
                ulonglong2 hv = hp[i];
                ffma2(acc01, wp[2 * i],     hv.x);
                ffma2(acc23, wp[2 * i + 1], hv.y);
            }
            float a0, a1, a2, a3;
            unpack2(acc01, a0, a1);
            unpack2(acc23, a2, a3);
            r = (a0 + a1) + (a2 + a3);
        }
        // seg-reduce within each aligned 8-lane group
        r += __shfl_xor_sync(0xffffffffu, r, 1);
        r += __shfl_xor_sync(0xffffffffu, r, 2);
        r += __shfl_xor_sync(0xffffffffu, r, 4);
        // warp-local gather: recurrent sums from lanes 0/8/16, X from 24/25/26
        const float rz = __shfl_sync(0xffffffffu, r, 0);
        const float rr = __shfl_sync(0xffffffffu, r, 8);
        const float rh = __shfl_sync(0xffffffffu, r, 16);
        const float xz = __shfl_sync(0xffffffffu, xv, 24);
        const float xr = __shfl_sync(0xffffffffu, xv, 25);
        const float xh = __shfl_sync(0xffffffffu, xv, 26);

        if (lane == 0) {
            const float zt = sigmoidf_(xz + rz + brz);
            const float rt = sigmoidf_(xr + rr + brr);
            const float hh = sigmoidf_(xh + rt * (rh + brh));
            const float hn = zt * hprev + (1.0f - zt) * hh;
            hprev = hn;
            const int l = blk * HPC + wj;
            st_rel64(&g_hs[b ^ 1][l], pack_hf(hn, (unsigned)(t + 1)));  // publish FIRST
            sh_h[b ^ 1][(l >> 6) * 68 + (l & 63)] = hn;                 // own slice, next buf
            g_seq[(size_t)t * HH + l] = hn;
        }
        if (isXl && t + 1 < TT)                // issue X[t+1] in gate shadow
            xv = g_X[(size_t)(t + 1) * H3 + xgc];
        // no second barrier: sh_h is parity double-buffered; any writer of
        // buf b at step t+2 is beyond bar1(t+1), which postdates all step-t
        // readers of buf b.
    }

    if (lane == 0) out[HT_OFF + blk * HPC + wj] = hprev;
}

// ---------------- policy softmax + value head ----------------
__global__ __launch_bounds__(256)
void policy_value_kernel(const float* __restrict__ Wp, const float* __restrict__ bp,
                         const float* __restrict__ Wv, const float* __restrict__ bv,
                         float* __restrict__ out)
{
    __shared__ float srow[8][HH];
    const int warp = threadIdx.x >> 5;
    const int lane = threadIdx.x & 31;
    const int t = blockIdx.x * 8 + warp;

    const float4* rp = (const float4*)&g_seq[(size_t)t * HH];
    float4* sp = (float4*)&srow[warp][0];
    for (int i = lane; i < HH / 4; i += 32) sp[i] = rp[i];
    __syncwarp();

    const float* wcol; int stride; float acc;
    if (lane < AA)       { wcol = Wp + lane; stride = AA; acc = bp[lane]; }
    else if (lane == AA) { wcol = Wv;        stride = 1;  acc = bv[0];    }
    else                 { wcol = Wv;        stride = 0;  acc = 0.0f;     }

    #pragma unroll 4
    for (int k = 0; k < HH; k++)
        acc = fmaf(srow[warp][k], wcol[(size_t)k * stride], acc);

    float lv = (lane < AA) ? acc : -INFINITY;
    float m = lv;
    #pragma unroll
    for (int o = 16; o; o >>= 1) m = fmaxf(m, __shfl_xor_sync(0xffffffffu, m, o));
    float e = (lane < AA) ? __expf(acc - m) : 0.0f;
    float sum = e;
    #pragma unroll
    for (int o = 16; o; o >>= 1) sum += __shfl_xor_sync(0xffffffffu, sum, o);

    if (lane < AA)  out[P_OFF + (size_t)t * AA + lane] = e / sum;
    if (lane == AA) out[V_OFF + t] = acc;
}

// ---------------- launch ----------------
extern "C" void kernel_launch(void* const* d_in, const int* in_sizes, int n_in,
                              void* d_out, int out_size)
{
    (void)in_sizes; (void)n_in; (void)out_size;
    const float* x    = (const float*)d_in[0];
    const float* ph   = (const float*)d_in[1];
    const float* W1   = (const float*)d_in[2];
    const float* b1   = (const float*)d_in[3];
    const float* W2   = (const float*)d_in[4];
    const float* b2   = (const float*)d_in[5];
    const float* Wg   = (const float*)d_in[6];
    const float* Ug   = (const float*)d_in[7];
    const float* bg   = (const float*)d_in[8];
    const float* Wp   = (const float*)d_in[9];
    const float* bp   = (const float*)d_in[10];
    const float* Wv   = (const float*)d_in[11];
    const float* bv   = (const float*)d_in[12];
    float* out = (float*)d_out;

    float *z1, *z2, *X;
    cudaGetSymbolAddress((void**)&z1, g_z1);
    cudaGetSymbolAddress((void**)&z2, g_z2);
    cudaGetSymbolAddress((void**)&X,  g_X);

    sgemm_bias<true ><<<dim3(DD/128, TT/128), 256>>>(x,  W1, b1, z1, TT, DD, DIN);
    sgemm_bias<true ><<<dim3(DD/128, TT/128), 256>>>(z1, W2, b2, z2, TT, DD, DD);
    sgemm_bias<false><<<dim3(H3/128, TT/128), 256>>>(z2, Wg, bg, X,  TT, H3, DD);

    init_kernel<<<1, HH>>>(ph);
    gru_kernel<<<GC, GTHREADS>>>(Ug, bg, ph, out);
    policy_value_kernel<<<TT/8, 256>>>(Wp, bp, Wv, bv, out);
}